// round 3
// baseline (speedup 1.0000x reference)
#include <cuda_runtime.h>

// IF spiking neuron, T=4 timesteps.
// x: [T*B, C, H, W] fp32, viewed as [T, B*C*H*W]. Per element-column:
//   mem = 0.5*thresh; for t: mem += x_t; spike = (mem>=thresh)*thresh; mem -= spike; out_t = spike.
// Pure HBM-streaming: 4 independent vectorized loads per thread, 4 stores.

#define T_STEPS 4

__global__ __launch_bounds__(256) void if_kernel(
    const float4* __restrict__ x,
    float4* __restrict__ out,
    const float* __restrict__ thresh_p,
    int n_vec_per_t)   // (B*C*H*W)/4
{
    int i = blockIdx.x * blockDim.x + threadIdx.x;
    if (i >= n_vec_per_t) return;

    const float th = __ldg(thresh_p);
    const float half_th = 0.5f * th;

    // Front-batch all 4 timestep loads (independent addresses -> MLP=4).
    float4 x0 = x[0 * (size_t)n_vec_per_t + i];
    float4 x1 = x[1 * (size_t)n_vec_per_t + i];
    float4 x2 = x[2 * (size_t)n_vec_per_t + i];
    float4 x3 = x[3 * (size_t)n_vec_per_t + i];

    float4 m = make_float4(half_th, half_th, half_th, half_th);
    float4 s;

    // t = 0
    m.x += x0.x; m.y += x0.y; m.z += x0.z; m.w += x0.w;
    s.x = (m.x >= th) ? th : 0.0f;  m.x -= s.x;
    s.y = (m.y >= th) ? th : 0.0f;  m.y -= s.y;
    s.z = (m.z >= th) ? th : 0.0f;  m.z -= s.z;
    s.w = (m.w >= th) ? th : 0.0f;  m.w -= s.w;
    out[0 * (size_t)n_vec_per_t + i] = s;

    // t = 1
    m.x += x1.x; m.y += x1.y; m.z += x1.z; m.w += x1.w;
    s.x = (m.x >= th) ? th : 0.0f;  m.x -= s.x;
    s.y = (m.y >= th) ? th : 0.0f;  m.y -= s.y;
    s.z = (m.z >= th) ? th : 0.0f;  m.z -= s.z;
    s.w = (m.w >= th) ? th : 0.0f;  m.w -= s.w;
    out[1 * (size_t)n_vec_per_t + i] = s;

    // t = 2
    m.x += x2.x; m.y += x2.y; m.z += x2.z; m.w += x2.w;
    s.x = (m.x >= th) ? th : 0.0f;  m.x -= s.x;
    s.y = (m.y >= th) ? th : 0.0f;  m.y -= s.y;
    s.z = (m.z >= th) ? th : 0.0f;  m.z -= s.z;
    s.w = (m.w >= th) ? th : 0.0f;  m.w -= s.w;
    out[2 * (size_t)n_vec_per_t + i] = s;

    // t = 3
    m.x += x3.x; m.y += x3.y; m.z += x3.z; m.w += x3.w;
    s.x = (m.x >= th) ? th : 0.0f;
    s.y = (m.y >= th) ? th : 0.0f;
    s.z = (m.z >= th) ? th : 0.0f;
    s.w = (m.w >= th) ? th : 0.0f;
    out[3 * (size_t)n_vec_per_t + i] = s;
}

extern "C" void kernel_launch(void* const* d_in, const int* in_sizes, int n_in,
                              void* d_out, int out_size) {
    const float* x = (const float*)d_in[0];
    const float* thresh = (const float*)d_in[1];
    // d_in[2] is T (known = 4 from problem shape; total/per_t derived from sizes)

    int n_total = in_sizes[0];            // T * B * C * H * W = 33,554,432
    int n_per_t = n_total / T_STEPS;      // 8,388,608
    int n_vec_per_t = n_per_t / 4;        // 2,097,152 float4 columns

    int threads = 256;
    int blocks = (n_vec_per_t + threads - 1) / threads;

    if_kernel<<<blocks, threads>>>(
        (const float4*)x, (float4*)d_out, thresh, n_vec_per_t);
}

// round 4
// speedup vs baseline: 1.0014x; 1.0014x over previous
#include <cuda_runtime.h>

// IF spiking neuron, T=4 timesteps, pure HBM streaming.
// Round-3 changes vs round-1:
//  - __ldcs / __stcs (evict-first) on all traffic: zero reuse, keep L2 clean.
//  - 2 float4 columns per thread: 8 independent LDG.128 front-batched (MLP=8),
//    half the threads, amortized indexing.

#define T_STEPS 4
#define VPT 2  // float4 columns per thread

__global__ __launch_bounds__(256) void if_kernel(
    const float4* __restrict__ x,
    float4* __restrict__ out,
    const float* __restrict__ thresh_p,
    int n_vec_per_t)   // (B*C*H*W)/4
{
    const int tid    = blockIdx.x * blockDim.x + threadIdx.x;
    const int stride = gridDim.x * blockDim.x;   // n_vec_per_t / VPT (exact)

    const float th = __ldg(thresh_p);
    const float half_th = 0.5f * th;

    // Front-batch all VPT*T loads — independent addresses, MLP = 8.
    float4 xv[VPT][T_STEPS];
#pragma unroll
    for (int v = 0; v < VPT; v++) {
        size_t i = (size_t)tid + (size_t)v * stride;
        if (i < (size_t)n_vec_per_t) {
#pragma unroll
            for (int t = 0; t < T_STEPS; t++)
                xv[v][t] = __ldcs(&x[(size_t)t * n_vec_per_t + i]);
        }
    }

#pragma unroll
    for (int v = 0; v < VPT; v++) {
        size_t i = (size_t)tid + (size_t)v * stride;
        if (i >= (size_t)n_vec_per_t) continue;

        float4 m = make_float4(half_th, half_th, half_th, half_th);
#pragma unroll
        for (int t = 0; t < T_STEPS; t++) {
            float4 s;
            m.x += xv[v][t].x;  s.x = (m.x >= th) ? th : 0.0f;  m.x -= s.x;
            m.y += xv[v][t].y;  s.y = (m.y >= th) ? th : 0.0f;  m.y -= s.y;
            m.z += xv[v][t].z;  s.z = (m.z >= th) ? th : 0.0f;  m.z -= s.z;
            m.w += xv[v][t].w;  s.w = (m.w >= th) ? th : 0.0f;  m.w -= s.w;
            __stcs(&out[(size_t)t * n_vec_per_t + i], s);
        }
    }
}

extern "C" void kernel_launch(void* const* d_in, const int* in_sizes, int n_in,
                              void* d_out, int out_size) {
    const float* x = (const float*)d_in[0];
    const float* thresh = (const float*)d_in[1];

    int n_total = in_sizes[0];            // T * B * C * H * W = 33,554,432
    int n_per_t = n_total / T_STEPS;      // 8,388,608
    int n_vec_per_t = n_per_t / 4;        // 2,097,152 float4 columns

    int threads = 256;
    int total_threads = (n_vec_per_t + VPT - 1) / VPT;   // 1,048,576
    int blocks = (total_threads + threads - 1) / threads; // 4096

    if_kernel<<<blocks, threads>>>(
        (const float4*)x, (float4*)d_out, thresh, n_vec_per_t);
}